// round 16
// baseline (speedup 1.0000x reference)
#include <cuda_runtime.h>
#include <math.h>

#define BB 4096
#define DD 2048
#define KK 8
#define PCOLS 25   // 3K+1

constexpr float RMIN = -5.0f;
constexpr float RMAX = 5.0f;
constexpr float MIN_BIN = 1e-3f;
constexpr float MIN_SLOPE = 1e-3f;
constexpr float MAX_SLOPE = 10.0f;

// Normalized quadratic-rational coefficients per (d,bin), in xc basis:
//   den'(xc) = xc^2 + a1*xc + a0          (true den / a2)
//   y  = Y'(xc) / den'(xc)                (Y' = Y / a2, quadratic)
//   dv = D'(xc) / den'(xc)^2              (D' = D / a2^2, quadratic)
// F1 = {a1, a0, Y2', Y1'}   F2 = {Y0', D2', D1', D0'}
__device__ float4 g_f1[8 * DD];
__device__ float4 g_f2[8 * DD];
// Interior knots x_k[1..7], SoA [7][DD].
__device__ float  g_knots[7 * DD];
// Tail slopes {s0, sK} per d.
__device__ float2 g_tail[DD];

// Warp-per-d normalization: lane j holds param j (j<25).
__global__ void __launch_bounds__(256) norm_kernel(const float* __restrict__ params,
                                                   float* __restrict__ ld_out) {
    const int lane = threadIdx.x & 31;
    const int d = (blockIdx.x * blockDim.x + threadIdx.x) >> 5;

    const float* p = params + (size_t)d * PCOLS;
    const float raw = (lane < PCOLS) ? p[lane] : 0.f;
    const float sig = 1.f / (1.f + __expf(-raw));

    float gs = sig;
    gs += __shfl_xor_sync(0xffffffffu, gs, 4);
    gs += __shfl_xor_sync(0xffffffffu, gs, 2);
    gs += __shfl_xor_sync(0xffffffffu, gs, 1);

    const float rem = (RMAX - RMIN) - KK * MIN_BIN;
    const float val = MIN_BIN + sig * (rem / gs);                  // width/height
    const float slope = MIN_SLOPE + sig * (MAX_SLOPE - MIN_SLOPE);

    float scan = val;
    float t;
    t = __shfl_up_sync(0xffffffffu, scan, 1); if ((lane & 7) >= 1) scan += t;
    t = __shfl_up_sync(0xffffffffu, scan, 2); if ((lane & 7) >= 2) scan += t;
    t = __shfl_up_sync(0xffffffffu, scan, 4); if ((lane & 7) >= 4) scan += t;

    const int j = lane & 7;
    const float ht     = __shfl_sync(0xffffffffu, val,   8 + j);
    const float ht_inc = __shfl_sync(0xffffffffu, scan,  8 + j);
    const float dk     = __shfl_sync(0xffffffffu, slope, 16 + j);   // slope_j
    const float dk1    = __shfl_sync(0xffffffffu, slope, 17 + j);   // slope_j+1
    const float sK     = __shfl_sync(0xffffffffu, slope, 24);       // slope_K

    if (lane < 8) {
        const float rw   = 1.f / val;
        const float knot = RMIN + scan - val;      // x_knot_j
        const float cc   = -knot * rw;             // xi = rw*xc + cc
        const float s    = ht * rw;
        const float A    = dk + dk1 - 2.f * s;
        const float sd   = s - dk;
        const float yk   = RMIN + ht_inc - ht;     // y_k
        const float s2   = s * s;

        // xi-basis quadratics (q2, q1, q0)
        const float d2i = -A,        d1i = A,            d0i = s;
        const float Y2i = ht * sd - yk * A;
        const float Y1i = yk * A + ht * dk;
        const float Y0i = yk * s;
        const float D2i = s2 * A;
        const float D1i = 2.f * s2 * sd;
        const float D0i = s2 * dk;

        // convert q(xi) -> q(xc): xi = rw*xc + cc
        // qc2 = q2*rw^2 ; qc1 = rw*(2*q2*cc + q1) ; qc0 = (q2*cc + q1)*cc + q0
        const float rw2 = rw * rw;
        const float a2  = d2i * rw2;
        const float a1  = rw * (2.f * d2i * cc + d1i);
        const float a0  = (d2i * cc + d1i) * cc + d0i;
        const float Yc2 = Y2i * rw2;
        const float Yc1 = rw * (2.f * Y2i * cc + Y1i);
        const float Yc0 = (Y2i * cc + Y1i) * cc + Y0i;
        const float Dc2 = D2i * rw2;
        const float Dc1 = rw * (2.f * D2i * cc + D1i);
        const float Dc0 = (D2i * cc + D1i) * cc + D0i;

        // normalize: den/a2 has leading coeff 1; Y/a2; D/a2^2
        const float ia  = 1.f / a2;
        const float ia2 = ia * ia;
        g_f1[lane * DD + d] = make_float4(a1 * ia, a0 * ia, Yc2 * ia, Yc1 * ia);
        g_f2[lane * DD + d] = make_float4(Yc0 * ia, Dc2 * ia2, Dc1 * ia2, Dc0 * ia2);
        if (lane < 7) g_knots[lane * DD + d] = RMIN + scan;
        if (lane == 0) g_tail[d] = make_float2(dk, sK);   // lane0's dk == slope_0
    }

    const int g = blockIdx.x * blockDim.x + threadIdx.x;
    if (g < BB) ld_out[g] = 0.f;
}

#define DT 256        // columns per CTA (== blockDim.x)
#define NCHUNK 512    // total row-chunks of 8 (BB/8)
#define GY 55         // 8*55=440 CTAs <= 444 capacity @3/SM, one wave

__global__ void __launch_bounds__(DT, 3) eval_kernel(const float* __restrict__ x,
                                                     float* __restrict__ y,
                                                     float* __restrict__ ld_out) {
    __shared__ float4 smA[8 * DT];   // 32 KB
    __shared__ float4 smB[8 * DT];   // 32 KB  (64 KB total; 3 CTAs/SM = 192 KB)

    const int tid = threadIdx.x;
    const int lane = tid & 31;
    const int d = blockIdx.x * DT + tid;

#pragma unroll
    for (int j = 0; j < 8; j++) {
        smA[j * DT + tid] = g_f1[j * DD + d];
        smB[j * DT + tid] = g_f2[j * DD + d];
    }

    const float v1 = g_knots[0 * DD + d];
    const float v2 = g_knots[1 * DD + d];
    const float v3 = g_knots[2 * DD + d];
    const float v4 = g_knots[3 * DD + d];
    const float v5 = g_knots[4 * DD + d];
    const float v6 = g_knots[5 * DD + d];
    const float v7 = g_knots[6 * DD + d];
    const float2 tl = g_tail[d];       // {s0, sK}
    __syncthreads();

    // lane-dependent constants for the transpose reduction
    const bool k4 = (lane & 16) != 0;
    const bool k2 = (lane & 8)  != 0;
    const bool k1 = (lane & 4)  != 0;
    const int  red_row = ((lane >> 4) & 1) * 4 + ((lane >> 3) & 1) * 2 + ((lane >> 2) & 1);

    // persistent grid-stride over row-chunks: single wave
    for (int c = blockIdx.y; c < NCHUNK; c += GY) {
        const int b0 = c * 8;
        const float* xp = x + (size_t)b0 * DD + d;
        float*       yp = y + (size_t)b0 * DD + d;

        // front-batch the 8 global loads (MLP=8)
        float xin[8];
#pragma unroll
        for (int r = 0; r < 8; r++) xin[r] = __ldg(&xp[r * DD]);

        float dv[8];
#pragma unroll
        for (int r = 0; r < 8; r++) {
            const float xv = xin[r];
            // clamp: rational eval at xc is exact at both edges (deriv = s0 / sK)
            const float xc = fminf(fmaxf(xv, RMIN), RMAX);

            // 3-level binary search
            int bin = 0;
            if (xc >= v4) bin = 4;
            const float c2 = (bin & 4) ? v6 : v2;
            if (xc >= c2) bin += 2;
            const float c1 = (bin & 4) ? ((bin & 2) ? v7 : v5)
                                       : ((bin & 2) ? v3 : v1);
            if (xc >= c1) bin += 1;

            // two conflict-free LDS.128
            const int idx = bin * DT + tid;
            const float4 f1 = smA[idx];   // {a1, a0, Y2, Y1}
            const float4 f2 = smB[idx];   // {Y0, D2, D1, D0}

            const float den  = fmaf(xc + f1.x, xc, f1.y);
            const float rden = __fdividef(1.f, den);
            const float Y    = fmaf(fmaf(f1.z, xc, f1.w), xc, f2.x);
            const float D    = fmaf(fmaf(f2.y, xc, f2.z), xc, f2.w);

            const float rden2 = rden * rden;
            dv[r] = D * rden2;                 // raw derivative; log deferred

            float yv = Y * rden;
            // linear tail extension: (x - xc) is 0 in-range
            const float tail = xv - xc;
            yv = fmaf(tail, (xv < 0.f) ? tl.x : tl.y, yv);

            yp[r * DD] = yv;
        }

        // Transpose-reduce: stages 1-3 MULTIPLY raw derivatives, ONE log per 16
        // elements, stages 4-5 ADD logs.
        float w4[4];
#pragma unroll
        for (int i = 0; i < 4; i++) {
            const float keep = k4 ? dv[i + 4] : dv[i];
            const float send = k4 ? dv[i] : dv[i + 4];
            w4[i] = keep * __shfl_xor_sync(0xffffffffu, send, 16);
        }
        float w2[2];
#pragma unroll
        for (int i = 0; i < 2; i++) {
            const float keep = k2 ? w4[i + 2] : w4[i];
            const float send = k2 ? w4[i] : w4[i + 2];
            w2[i] = keep * __shfl_xor_sync(0xffffffffu, send, 8);
        }
        const float pz = (k1 ? w2[1] : w2[0]) * __shfl_xor_sync(0xffffffffu, k1 ? w2[0] : w2[1], 4);

        float z = __logf(pz);           // one log per 16 elements
        z += __shfl_xor_sync(0xffffffffu, z, 2);
        z += __shfl_xor_sync(0xffffffffu, z, 1);

        if ((lane & 3) == 0) atomicAdd(&ld_out[b0 + red_row], z);
    }
}

extern "C" void kernel_launch(void* const* d_in, const int* in_sizes, int n_in,
                              void* d_out, int out_size) {
    const float* x;
    const float* params;
    if (in_sizes[0] == BB * DD) { x = (const float*)d_in[0]; params = (const float*)d_in[1]; }
    else                        { x = (const float*)d_in[1]; params = (const float*)d_in[0]; }

    float* y_out  = (float*)d_out;              // [B, D]
    float* ld_out = y_out + (size_t)BB * DD;    // [B]

    static bool configured = false;
    if (!configured) {
        cudaFuncSetAttribute(eval_kernel, cudaFuncAttributePreferredSharedMemoryCarveout, 100);
        configured = true;
    }

    norm_kernel<<<(DD * 32) / 256, 256>>>(params, ld_out);   // warp-per-d
    dim3 grid(DD / DT, GY);
    eval_kernel<<<grid, DT>>>(x, y_out, ld_out);
}

// round 17
// speedup vs baseline: 1.0904x; 1.0904x over previous
#include <cuda_runtime.h>
#include <math.h>

#define BB 4096
#define DD 2048
#define KK 8
#define PCOLS 25   // 3K+1

constexpr float RMIN = -5.0f;
constexpr float RMAX = 5.0f;
constexpr float MIN_BIN = 1e-3f;
constexpr float MIN_SLOPE = 1e-3f;
constexpr float MAX_SLOPE = 10.0f;

// Normalized quadratic-rational coefficients per (d,bin), in xc basis:
//   den'(xc) = xc^2 + a1*xc + a0 ; y = Y'(xc)/den' ; dv = D'(xc)/den'^2
// F1 = {a1, a0, Y2', Y1'}   F2 = {Y0', D2', D1', D0'}
__device__ float4 g_f1[8 * DD];
__device__ float4 g_f2[8 * DD];
__device__ float  g_knots[7 * DD];
__device__ float2 g_tail[DD];

// Warp-per-d normalization: lane j holds param j (j<25).
__global__ void __launch_bounds__(256) norm_kernel(const float* __restrict__ params,
                                                   float* __restrict__ ld_out) {
    const int lane = threadIdx.x & 31;
    const int d = (blockIdx.x * blockDim.x + threadIdx.x) >> 5;

    const float* p = params + (size_t)d * PCOLS;
    const float raw = (lane < PCOLS) ? p[lane] : 0.f;
    const float sig = 1.f / (1.f + __expf(-raw));

    float gs = sig;
    gs += __shfl_xor_sync(0xffffffffu, gs, 4);
    gs += __shfl_xor_sync(0xffffffffu, gs, 2);
    gs += __shfl_xor_sync(0xffffffffu, gs, 1);

    const float rem = (RMAX - RMIN) - KK * MIN_BIN;
    const float val = MIN_BIN + sig * (rem / gs);
    const float slope = MIN_SLOPE + sig * (MAX_SLOPE - MIN_SLOPE);

    float scan = val;
    float t;
    t = __shfl_up_sync(0xffffffffu, scan, 1); if ((lane & 7) >= 1) scan += t;
    t = __shfl_up_sync(0xffffffffu, scan, 2); if ((lane & 7) >= 2) scan += t;
    t = __shfl_up_sync(0xffffffffu, scan, 4); if ((lane & 7) >= 4) scan += t;

    const int j = lane & 7;
    const float ht     = __shfl_sync(0xffffffffu, val,   8 + j);
    const float ht_inc = __shfl_sync(0xffffffffu, scan,  8 + j);
    const float dk     = __shfl_sync(0xffffffffu, slope, 16 + j);
    const float dk1    = __shfl_sync(0xffffffffu, slope, 17 + j);
    const float sK     = __shfl_sync(0xffffffffu, slope, 24);

    if (lane < 8) {
        const float rw   = 1.f / val;
        const float knot = RMIN + scan - val;
        const float cc   = -knot * rw;
        const float s    = ht * rw;
        const float A    = dk + dk1 - 2.f * s;
        const float sd   = s - dk;
        const float yk   = RMIN + ht_inc - ht;
        const float s2   = s * s;

        const float d2i = -A,  d1i = A,  d0i = s;
        const float Y2i = ht * sd - yk * A;
        const float Y1i = yk * A + ht * dk;
        const float Y0i = yk * s;
        const float D2i = s2 * A;
        const float D1i = 2.f * s2 * sd;
        const float D0i = s2 * dk;

        const float rw2 = rw * rw;
        const float a2  = d2i * rw2;
        const float a1  = rw * (2.f * d2i * cc + d1i);
        const float a0  = (d2i * cc + d1i) * cc + d0i;
        const float Yc2 = Y2i * rw2;
        const float Yc1 = rw * (2.f * Y2i * cc + Y1i);
        const float Yc0 = (Y2i * cc + Y1i) * cc + Y0i;
        const float Dc2 = D2i * rw2;
        const float Dc1 = rw * (2.f * D2i * cc + D1i);
        const float Dc0 = (D2i * cc + D1i) * cc + D0i;

        const float ia  = 1.f / a2;
        const float ia2 = ia * ia;
        g_f1[lane * DD + d] = make_float4(a1 * ia, a0 * ia, Yc2 * ia, Yc1 * ia);
        g_f2[lane * DD + d] = make_float4(Yc0 * ia, Dc2 * ia2, Dc1 * ia2, Dc0 * ia2);
        if (lane < 7) g_knots[lane * DD + d] = RMIN + scan;
        if (lane == 0) g_tail[d] = make_float2(dk, sK);
    }

    const int g = blockIdx.x * blockDim.x + threadIdx.x;
    if (g < BB) ld_out[g] = 0.f;
}

#define DT 256        // columns per CTA (== blockDim.x)
#define RC 16         // rows per chunk
#define NCHUNK 256    // total row-chunks (BB/RC)
#define GY 55         // 8*55=440 CTAs <= 444 capacity @3/SM, one wave

__global__ void __launch_bounds__(DT, 3) eval_kernel(const float* __restrict__ x,
                                                     float* __restrict__ y,
                                                     float* __restrict__ ld_out) {
    __shared__ float4 smA[8 * DT];   // 32 KB
    __shared__ float4 smB[8 * DT];   // 32 KB

    const int tid = threadIdx.x;
    const int lane = tid & 31;
    const int d = blockIdx.x * DT + tid;

#pragma unroll
    for (int j = 0; j < 8; j++) {
        smA[j * DT + tid] = g_f1[j * DD + d];
        smB[j * DT + tid] = g_f2[j * DD + d];
    }

    const float v1 = g_knots[0 * DD + d];
    const float v2 = g_knots[1 * DD + d];
    const float v3 = g_knots[2 * DD + d];
    const float v4 = g_knots[3 * DD + d];
    const float v5 = g_knots[4 * DD + d];
    const float v6 = g_knots[5 * DD + d];
    const float v7 = g_knots[6 * DD + d];
    const float2 tl = g_tail[d];       // {s0, sK}
    __syncthreads();

    // lane bits for the 16-row transpose reduction
    const bool k16 = (lane & 16) != 0;
    const bool k8  = (lane & 8)  != 0;
    const bool k4  = (lane & 4)  != 0;
    const bool k2  = (lane & 2)  != 0;
    const int  red_row = ((lane >> 4) & 1) * 8 + ((lane >> 3) & 1) * 4
                       + ((lane >> 2) & 1) * 2 + ((lane >> 1) & 1);

    for (int c = blockIdx.y; c < NCHUNK; c += GY) {
        const int b0 = c * RC;
        const float* xp = x + (size_t)b0 * DD + d;
        float*       yp = y + (size_t)b0 * DD + d;

        // front-batch 16 global loads (MLP=16)
        float xin[RC];
#pragma unroll
        for (int r = 0; r < RC; r++) xin[r] = __ldg(&xp[r * DD]);

        float dv[RC];
#pragma unroll
        for (int r = 0; r < RC; r++) {
            const float xv = xin[r];
            const float xc = fminf(fmaxf(xv, RMIN), RMAX);

            int bin = 0;
            if (xc >= v4) bin = 4;
            const float c2 = (bin & 4) ? v6 : v2;
            if (xc >= c2) bin += 2;
            const float c1 = (bin & 4) ? ((bin & 2) ? v7 : v5)
                                       : ((bin & 2) ? v3 : v1);
            if (xc >= c1) bin += 1;

            const int idx = bin * DT + tid;
            const float4 f1 = smA[idx];   // {a1, a0, Y2, Y1}
            const float4 f2 = smB[idx];   // {Y0, D2, D1, D0}

            const float den  = fmaf(xc + f1.x, xc, f1.y);
            const float rden = __fdividef(1.f, den);
            const float Y    = fmaf(fmaf(f1.z, xc, f1.w), xc, f2.x);
            const float D    = fmaf(fmaf(f2.y, xc, f2.z), xc, f2.w);

            dv[r] = D * (rden * rden);    // raw derivative; log deferred

            float yv = Y * rden;
            const float tail = xv - xc;   // 0 in-range
            yv = fmaf(tail, (xv < 0.f) ? tl.x : tl.y, yv);

            yp[r * DD] = yv;
        }

        // Transpose-reduce 16 rows: 4 mul-halving stages + final xor1 product,
        // ONE log per 32 elements, 1 atomic per row per warp.
        float w8[8];
#pragma unroll
        for (int i = 0; i < 8; i++) {
            const float keep = k16 ? dv[i + 8] : dv[i];
            const float send = k16 ? dv[i] : dv[i + 8];
            w8[i] = keep * __shfl_xor_sync(0xffffffffu, send, 16);
        }
        float w4[4];
#pragma unroll
        for (int i = 0; i < 4; i++) {
            const float keep = k8 ? w8[i + 4] : w8[i];
            const float send = k8 ? w8[i] : w8[i + 4];
            w4[i] = keep * __shfl_xor_sync(0xffffffffu, send, 8);
        }
        float w2[2];
#pragma unroll
        for (int i = 0; i < 2; i++) {
            const float keep = k4 ? w2[0] * 0.f + w4[i + 2] : w4[i];   // (avoid compiler confusion)
            const float send = k4 ? w4[i] : w4[i + 2];
            w2[i] = (k4 ? w4[i + 2] : w4[i]) * __shfl_xor_sync(0xffffffffu, send, 4);
            (void)keep;
        }
        float w1 = (k2 ? w2[1] : w2[0]) * __shfl_xor_sync(0xffffffffu, k2 ? w2[0] : w2[1], 2);
        const float pz = w1 * __shfl_xor_sync(0xffffffffu, w1, 1);

        const float z = __logf(pz);       // one log per 32 elements
        if ((lane & 1) == 0) atomicAdd(&ld_out[b0 + red_row], z);
    }
}

extern "C" void kernel_launch(void* const* d_in, const int* in_sizes, int n_in,
                              void* d_out, int out_size) {
    const float* x;
    const float* params;
    if (in_sizes[0] == BB * DD) { x = (const float*)d_in[0]; params = (const float*)d_in[1]; }
    else                        { x = (const float*)d_in[1]; params = (const float*)d_in[0]; }

    float* y_out  = (float*)d_out;              // [B, D]
    float* ld_out = y_out + (size_t)BB * DD;    // [B]

    static bool configured = false;
    if (!configured) {
        cudaFuncSetAttribute(eval_kernel, cudaFuncAttributePreferredSharedMemoryCarveout, 100);
        configured = true;
    }

    norm_kernel<<<(DD * 32) / 256, 256>>>(params, ld_out);   // warp-per-d
    dim3 grid(DD / DT, GY);
    eval_kernel<<<grid, DT>>>(x, y_out, ld_out);
}